// round 3
// baseline (speedup 1.0000x reference)
#include <cuda_runtime.h>

// MatrixVectorScaledDotProductAttention on GB300 — chunked 2-kernel version.
// q[512,128] f32, k[512,2048,128] f32, v[512,2048,128] f32.
// Output tuple: out[512,128] f32 then attn[512,2048] f32.
//
// Kernel1: 512 rows x 8 L-chunks = 4096 CTAs (evenly packs 148 SMs @ occ 4),
// each does a fused score + online-softmax + weighted-v pass over its chunk,
// writes raw scores to attn and (m, sum, acc[128]) partials to device scratch.
// Kernel2: 512 CTAs combine the 8 partials per row, write out, and rescale
// the attn row in place.

constexpr int NB = 512;
constexpr int L  = 2048;
constexpr int D  = 128;
constexpr float INV_T = 1.0f / 11.313708498984761f;  // 1/sqrt(128)

constexpr int CHUNKS = 8;
constexpr int CL     = L / CHUNKS;        // 256 rows per chunk

constexpr int THREADS = 256;
constexpr int WARPS   = THREADS / 32;

// Per-(row,chunk) softmax partials (allocation-free scratch).
__device__ float g_pm[NB * CHUNKS];           // chunk max
__device__ float g_ps[NB * CHUNKS];           // chunk sum of exp(s - m)
__device__ float g_pacc[NB * CHUNKS * D];     // chunk weighted-v accumulator

__global__ __launch_bounds__(THREADS, 4)
void mvsdpa_chunk_kernel(const float* __restrict__ q,
                         const float* __restrict__ k,
                         const float* __restrict__ v,
                         float* __restrict__ attn)   // [NB, L] — raw scores for now
{
    __shared__ float s[CL];                // raw scores for this chunk (1 KB)
    __shared__ float red_m[WARPS];
    __shared__ float red_s[WARPS];
    __shared__ float acc_s[WARPS * D];     // per-warp output partials (4 KB)

    const int b    = blockIdx.x / CHUNKS;
    const int c    = blockIdx.x % CHUNKS;
    const int l0   = c * CL;
    const int tid  = threadIdx.x;
    const int lane = tid & 31;
    const int w    = tid >> 5;

    const float4 q4 = *reinterpret_cast<const float4*>(q + (size_t)b * D + lane * 4);
    const float* kb = k + ((size_t)b * L + l0) * D;
    const float* vb = v + ((size_t)b * L + l0) * D;

    float m   = -1e30f;
    float sum = 0.f;
    float4 acc = make_float4(0.f, 0.f, 0.f, 0.f);

    #pragma unroll 4
    for (int l = w; l < CL; l += WARPS) {
        float4 k4 = *reinterpret_cast<const float4*>(kb + (size_t)l * D + lane * 4);
        float4 v4 = *reinterpret_cast<const float4*>(vb + (size_t)l * D + lane * 4);

        float p = k4.x * q4.x + k4.y * q4.y + k4.z * q4.z + k4.w * q4.w;
        #pragma unroll
        for (int o = 16; o > 0; o >>= 1)
            p += __shfl_xor_sync(0xffffffffu, p, o);
        float score = p * INV_T;
        if (lane == 0) s[l] = score;

        if (score > m) {                    // warp-uniform, rare
            float cr = __expf(m - score);
            sum *= cr;
            acc.x *= cr; acc.y *= cr; acc.z *= cr; acc.w *= cr;
            m = score;
        }
        float e = __expf(score - m);
        sum += e;
        acc.x += e * v4.x;
        acc.y += e * v4.y;
        acc.z += e * v4.z;
        acc.w += e * v4.w;
    }

    if (lane == 0) { red_m[w] = m; red_s[w] = sum; }
    __syncthreads();

    // CTA-level combine of the 8 warp partials (done redundantly per thread)
    float M = red_m[0];
    #pragma unroll
    for (int j = 1; j < WARPS; j++) M = fmaxf(M, red_m[j]);
    float sumc = 0.f;
    #pragma unroll
    for (int j = 0; j < WARPS; j++) sumc += red_s[j] * __expf(red_m[j] - M);

    const float scale = __expf(m - M);
    acc.x *= scale; acc.y *= scale; acc.z *= scale; acc.w *= scale;
    *reinterpret_cast<float4*>(acc_s + w * D + lane * 4) = acc;
    __syncthreads();

    // Raw scores -> attn chunk (coalesced float4)
    {
        const float4* s4p = reinterpret_cast<const float4*>(s);
        float4* a4p = reinterpret_cast<float4*>(attn + (size_t)b * L + l0);
        if (tid < CL / 4) a4p[tid] = s4p[tid];
    }

    // Partials out
    const int pc = b * CHUNKS + c;
    if (tid < D) {
        float o = 0.f;
        #pragma unroll
        for (int j = 0; j < WARPS; j++) o += acc_s[j * D + tid];
        g_pacc[(size_t)pc * D + tid] = o;
    }
    if (tid == 0) { g_pm[pc] = M; g_ps[pc] = sumc; }
}

__global__ __launch_bounds__(THREADS, 4)
void mvsdpa_combine_kernel(float* __restrict__ out,    // [NB, D]
                           float* __restrict__ attn)   // [NB, L] raw -> normalized
{
    const int b   = blockIdx.x;
    const int tid = threadIdx.x;

    // Every thread reads the 8 tiny partial headers (L2/L1-resident).
    float pm[CHUNKS], ps[CHUNKS];
    #pragma unroll
    for (int j = 0; j < CHUNKS; j++) {
        pm[j] = g_pm[b * CHUNKS + j];
        ps[j] = g_ps[b * CHUNKS + j];
    }
    float M = pm[0];
    #pragma unroll
    for (int j = 1; j < CHUNKS; j++) M = fmaxf(M, pm[j]);
    float sumtot = 0.f;
    #pragma unroll
    for (int j = 0; j < CHUNKS; j++) sumtot += ps[j] * __expf(pm[j] - M);
    const float inv = 1.0f / sumtot;

    // Combine output accumulators.
    if (tid < D) {
        float o = 0.f;
        #pragma unroll
        for (int j = 0; j < CHUNKS; j++)
            o += g_pacc[(size_t)(b * CHUNKS + j) * D + tid] * __expf(pm[j] - M);
        out[(size_t)b * D + tid] = o * inv;
    }

    // Rescale attn row: raw score -> exp(s - M) * inv.
    float4* a4p = reinterpret_cast<float4*>(attn + (size_t)b * L);
    #pragma unroll
    for (int i = tid; i < L / 4; i += THREADS) {
        float4 sv = a4p[i];
        float4 av;
        av.x = __expf(sv.x - M) * inv;
        av.y = __expf(sv.y - M) * inv;
        av.z = __expf(sv.z - M) * inv;
        av.w = __expf(sv.w - M) * inv;
        a4p[i] = av;
    }
}

extern "C" void kernel_launch(void* const* d_in, const int* in_sizes, int n_in,
                              void* d_out, int out_size) {
    const float* q = (const float*)d_in[0];
    const float* k = (const float*)d_in[1];
    const float* v = (const float*)d_in[2];
    float* out  = (float*)d_out;             // [NB, D]
    float* attn = (float*)d_out + NB * D;    // [NB, L]
    mvsdpa_chunk_kernel<<<NB * CHUNKS, THREADS>>>(q, k, v, attn);
    mvsdpa_combine_kernel<<<NB, THREADS>>>(out, attn);
}